// round 10
// baseline (speedup 1.0000x reference)
#include <cuda_runtime.h>
#include <math.h>
#include <stdint.h>

#define N_NODES 8192
#define F_IN    512
#define F_OUT   64
#define ALPHA   0.2f

#define TJ      32
#define JSPLIT  8
#define JQ      (N_NODES / JSPLIT)   // 1024
#define TILES_B (JQ / TJ)            // 32 tiles per block
#define ROWS_B  64                   // i-rows per block

// SMEM stage layout (bytes)
#define ADJ_STRIDE 144               // 36 ints per adj row (32 data + pad)
#define WH_STRIDE  288               // 72 floats per Wh row (64 data + pad)
#define WH_OFF     9216              // after 64 adj rows
#define S2_OFF     18432
#define STAGE      18560
#define RING       3
#define SMEM_SZ    (STAGE * RING)    // 55680 (x4 blocks = 222.7KB/SM)

// Scratch (no allocations allowed anywhere)
__device__ float g_Wh [N_NODES * F_OUT];
// tf32-rounded, column-permuted (see wh epilogue)
__device__ float g_WhB[N_NODES * F_OUT];
__device__ float g_s1 [N_NODES];
__device__ float g_s2 [N_NODES];
__device__ float g_s2max;
__device__ float g_part [JSPLIT][N_NODES * F_OUT];
__device__ float g_lpart[JSPLIT][N_NODES];

// ---- helpers ---------------------------------------------------------------
__device__ __forceinline__ uint32_t smem_u32(const void* p) {
    uint32_t r;
    asm("{ .reg .u64 t; cvta.to.shared.u64 t, %1; cvt.u32.u64 %0, t; }"
        : "=r"(r) : "l"(p));
    return r;
}
__device__ __forceinline__ void cp_async16(uint32_t dst, const void* src) {
    asm volatile("cp.async.cg.shared.global [%0], [%1], 16;"
                 :: "r"(dst), "l"(src) : "memory");
}
__device__ __forceinline__ void cp_commit() {
    asm volatile("cp.async.commit_group;" ::: "memory");
}
__device__ __forceinline__ void cp_wait1() {
    asm volatile("cp.async.wait_group 1;" ::: "memory");
}
__device__ __forceinline__ uint32_t to_tf32(float x) {
    uint32_t r;
    asm("cvt.rna.tf32.f32 %0, %1;" : "=r"(r) : "f"(x));
    return r;
}
__device__ __forceinline__ void mma_tf32(float* c, uint32_t a0, uint32_t a1,
                                         uint32_t a2, uint32_t a3,
                                         uint32_t b0, uint32_t b1) {
    asm volatile(
        "mma.sync.aligned.m16n8k8.row.col.f32.tf32.tf32.f32 "
        "{%0,%1,%2,%3}, {%4,%5,%6,%7}, {%8,%9}, {%0,%1,%2,%3};"
        : "+f"(c[0]), "+f"(c[1]), "+f"(c[2]), "+f"(c[3])
        : "r"(a0), "r"(a1), "r"(a2), "r"(a3), "r"(b0), "r"(b1));
}

// ---------------------------------------------------------------------------
// Kernel A: Wh = x @ W via tf32 mma.sync. Block = 64 rows x 64 cols, K=512.
// ---------------------------------------------------------------------------
#define XS_STR 36
#define WS_STR 72
__device__ __forceinline__ void wh_cp_wait1() {
    asm volatile("cp.async.wait_group 1;" ::: "memory");
}
__global__ __launch_bounds__(256) void wh_kernel(const float* __restrict__ x,
                                                 const float* __restrict__ W) {
    __shared__ __align__(16) float xs[2][64 * XS_STR];
    __shared__ __align__(16) float ws[2][32 * WS_STR];

    const int tid  = threadIdx.x;
    const int w    = tid >> 5, lane = tid & 31;
    const int wr   = w & 3,    wc   = w >> 2;
    const int g    = lane >> 2, tig = lane & 3;
    const int r0   = blockIdx.x * 64;
    const int r0l  = wr * 16 + g;
    const int r1l  = r0l + 8;

    const uint32_t xs0 = smem_u32(xs);
    const uint32_t ws0 = smem_u32(ws);

    auto prefetch = [&](int s) {
        if (s < 16) {
            int b = s & 1;
            int k0 = s * 32;
            #pragma unroll
            for (int c = tid; c < 512; c += 256) {     // x: 64 rows x 32 k
                int r = c >> 3, q = c & 7;
                cp_async16(xs0 + (b * 64 * XS_STR + r * XS_STR) * 4 + q * 16,
                           x + (size_t)(r0 + r) * F_IN + k0 + q * 4);
            }
            #pragma unroll
            for (int c = tid; c < 512; c += 256) {     // W: 32 k x 64 f
                int r = c >> 4, q = c & 15;
                cp_async16(ws0 + (b * 32 * WS_STR + r * WS_STR) * 4 + q * 16,
                           W + (size_t)(k0 + r) * F_OUT + q * 4);
            }
        }
        cp_commit();
    };

    float acc[4][4] = {};
    prefetch(0);

    for (int s = 0; s < 16; ++s) {
        prefetch(s + 1);
        wh_cp_wait1();
        __syncthreads();

        const float* xp = &xs[s & 1][0];
        const float* wp = &ws[s & 1][0];

        #pragma unroll
        for (int kc = 0; kc < 4; ++kc) {
            uint32_t a0 = to_tf32(xp[r0l * XS_STR + kc * 8 + tig]);
            uint32_t a1 = to_tf32(xp[r1l * XS_STR + kc * 8 + tig]);
            uint32_t a2 = to_tf32(xp[r0l * XS_STR + kc * 8 + tig + 4]);
            uint32_t a3 = to_tf32(xp[r1l * XS_STR + kc * 8 + tig + 4]);
            #pragma unroll
            for (int n = 0; n < 4; ++n) {
                int f = wc * 32 + n * 8 + g;
                uint32_t b0 = to_tf32(wp[(kc * 8 + tig)     * WS_STR + f]);
                uint32_t b1 = to_tf32(wp[(kc * 8 + tig + 4) * WS_STR + f]);
                mma_tf32(acc[n], a0, a1, a2, a3, b0, b1);
            }
        }
        __syncthreads();
    }

    #pragma unroll
    for (int n = 0; n < 4; ++n) {
        int f = wc * 32 + n * 8 + tig * 2;   // original columns f, f+1
        size_t o0 = (size_t)(r0 + r0l) * F_OUT + f;
        size_t o1 = (size_t)(r0 + r1l) * F_OUT + f;
        *(float2*)&g_Wh[o0] = make_float2(acc[n][0], acc[n][1]);
        *(float2*)&g_Wh[o1] = make_float2(acc[n][2], acc[n][3]);
        int p0 = wc * 32 + tig * 8 + n;
        g_WhB[(size_t)(r0 + r0l) * F_OUT + p0]     = __uint_as_float(to_tf32(acc[n][0]));
        g_WhB[(size_t)(r0 + r0l) * F_OUT + p0 + 4] = __uint_as_float(to_tf32(acc[n][1]));
        g_WhB[(size_t)(r0 + r1l) * F_OUT + p0]     = __uint_as_float(to_tf32(acc[n][2]));
        g_WhB[(size_t)(r0 + r1l) * F_OUT + p0 + 4] = __uint_as_float(to_tf32(acc[n][3]));
    }
}

// ---------------------------------------------------------------------------
// Kernel B: s1 = Wh @ a1, s2 = Wh @ a2
// ---------------------------------------------------------------------------
__global__ __launch_bounds__(256) void s_kernel(const float* __restrict__ A) {
    const int row  = blockIdx.x * 8 + (threadIdx.x >> 5);
    const int lane = threadIdx.x & 31;
    float w0 = g_Wh[row * F_OUT + lane];
    float w1 = g_Wh[row * F_OUT + lane + 32];
    float v1 = w0 * A[lane]         + w1 * A[lane + 32];
    float v2 = w0 * A[F_OUT + lane] + w1 * A[F_OUT + lane + 32];
    #pragma unroll
    for (int off = 16; off; off >>= 1) {
        v1 += __shfl_xor_sync(0xFFFFFFFFu, v1, off);
        v2 += __shfl_xor_sync(0xFFFFFFFFu, v2, off);
    }
    if (lane == 0) { g_s1[row] = v1; g_s2[row] = v2; }
}

// ---------------------------------------------------------------------------
// Kernel B2: g_s2max = max(g_s2)
// ---------------------------------------------------------------------------
__global__ __launch_bounds__(1024) void s2max_kernel() {
    __shared__ float sm[32];
    const int tid = threadIdx.x;
    float m = -INFINITY;
    for (int i = tid; i < N_NODES; i += 1024) m = fmaxf(m, g_s2[i]);
    #pragma unroll
    for (int off = 16; off; off >>= 1)
        m = fmaxf(m, __shfl_xor_sync(0xFFFFFFFFu, m, off));
    if ((tid & 31) == 0) sm[tid >> 5] = m;
    __syncthreads();
    if (tid < 32) {
        m = sm[tid];
        #pragma unroll
        for (int off = 16; off; off >>= 1)
            m = fmaxf(m, __shfl_xor_sync(0xFFFFFFFFu, m, off));
        if (tid == 0) g_s2max = m;
    }
}

// ---------------------------------------------------------------------------
// Kernel C: fused attention via mma.sync tf32 (m16n8k8).
// grid = 128 i-blocks x 8 j-slices = 1024 blocks, 4 blocks/SM (ring 3,
// regs capped at 64 by launch_bounds). 8 warps = 4 row-tiles x 2 j-halves.
// ---------------------------------------------------------------------------
__global__ __launch_bounds__(256, 4) void attn_kernel(const int* __restrict__ adj) {
    extern __shared__ __align__(1024) char smem[];
    const int tid  = threadIdx.x;
    const int w    = tid >> 5, lane = tid & 31;
    const int wr   = w & 3,    jh   = w >> 2;
    const int g    = lane >> 2, tig = lane & 3;
    const int i0   = (blockIdx.x >> 3) * ROWS_B;
    const int qh   = blockIdx.x & 7;
    const int j0b  = qh * JQ;
    const int r0l  = wr * 16 + g;
    const int r1l  = r0l + 8;

    const uint32_t sb = smem_u32(smem);

    // per-thread invariant offsets (bytes)
    const int pr  = tid >> 3, pq8 = tid & 7;      // adj prefetch row/quad
    const int wr_ = tid >> 4, wq  = tid & 15;     // WhB prefetch row/quad
    const uint32_t adj_dst0 = sb + pr * ADJ_STRIDE + pq8 * 16;
    const uint32_t adj_dst1 = adj_dst0 + 32 * ADJ_STRIDE;
    const uint32_t wh_dst0  = sb + WH_OFF + wr_ * WH_STRIDE + wq * 16;
    const uint32_t wh_dst1  = wh_dst0 + 16 * WH_STRIDE;
    const int      a_row0   = r0l * ADJ_STRIDE;
    const int      a_row1   = r1l * ADJ_STRIDE;

    // incrementing global sources
    const int* adj_src0 = adj + (size_t)(i0 + pr)      * N_NODES + j0b + pq8 * 4;
    const int* adj_src1 = adj + (size_t)(i0 + pr + 32) * N_NODES + j0b + pq8 * 4;
    const float* wh_src0 = g_WhB + (size_t)(j0b + wr_)      * F_OUT + wq * 4;
    const float* wh_src1 = g_WhB + (size_t)(j0b + wr_ + 16) * F_OUT + wq * 4;
    const float* s2_src  = g_s2 + j0b + (tid & 7) * 4;

    auto prefetch = [&](int t) {
        if (t < TILES_B) {
            uint32_t base = (uint32_t)((t % RING) * STAGE);
            int joff = t * TJ;
            cp_async16(adj_dst0 + base, adj_src0 + joff);
            cp_async16(adj_dst1 + base, adj_src1 + joff);
            cp_async16(wh_dst0 + base, wh_src0 + (size_t)joff * F_OUT);
            cp_async16(wh_dst1 + base, wh_src1 + (size_t)joff * F_OUT);
            if (tid < 8)
                cp_async16(sb + S2_OFF + base + tid * 16, s2_src + joff);
        }
        cp_commit();
    };

    const float s1_0 = g_s1[i0 + r0l];
    const float s1_1 = g_s1[i0 + r1l];
    const float s2m  = g_s2max;
    const float m0 = fmaxf(s1_0 + s2m, ALPHA * (s1_0 + s2m));
    const float m1 = fmaxf(s1_1 + s2m, ALPHA * (s1_1 + s2m));

    float acc[8][4] = {};
    float sum0 = 0.f, sum1 = 0.f;

    prefetch(0); prefetch(1);

    for (int t = 0; t < TILES_B; ++t) {
        cp_wait1();
        __syncthreads();
        prefetch(t + 2);     // refills slot (t-1)%3; reads of t-1 done pre-barrier

        const char*  base = smem + (t % RING) * STAGE;
        const float* s2p  = (const float*)(base + S2_OFF);
        const float* whp  = (const float*)(base + WH_OFF);

        // A fragments for this warp's 16-j half: 8 weights (2 rows x 4 j)
        uint32_t aw[2][4];
        #pragma unroll
        for (int kc = 0; kc < 2; ++kc) {
            #pragma unroll
            for (int h = 0; h < 2; ++h) {
                int j = jh * 16 + kc * 8 + tig + 4 * h;
                float s2v = s2p[j];
                int a0 = *(const int*)(base + a_row0 + j * 4);
                int a1 = *(const int*)(base + a_row1 + j * 4);
                float t0 = s1_0 + s2v;
                float t1 = s1_1 + s2v;
                float e0 = fmaxf(t0, ALPHA * t0);
                float e1 = fmaxf(t1, ALPHA * t1);
                float w0 = (a0 > 0) ? __expf(e0 - m0) : 0.f;
                float w1 = (a1 > 0) ? __expf(e1 - m1) : 0.f;
                sum0 += w0; sum1 += w1;
                aw[kc][2 * h]     = to_tf32(w0);
                aw[kc][2 * h + 1] = to_tf32(w1);
            }
        }

        // MMA over this warp's 16 j (2 k-chunks), full 64 f.
        #pragma unroll
        for (int kc = 0; kc < 2; ++kc) {
            int jr0 = jh * 16 + kc * 8 + tig;
            int jr1 = jr0 + 4;
            float4 bl0 = *(const float4*)&whp[jr0 * 72 + g * 4];
            float4 bh0 = *(const float4*)&whp[jr0 * 72 + 32 + g * 4];
            float4 bl1 = *(const float4*)&whp[jr1 * 72 + g * 4];
            float4 bh1 = *(const float4*)&whp[jr1 * 72 + 32 + g * 4];
            uint32_t a0 = aw[kc][0], a1 = aw[kc][1];
            uint32_t a2 = aw[kc][2], a3 = aw[kc][3];
            mma_tf32(acc[0], a0, a1, a2, a3, __float_as_uint(bl0.x), __float_as_uint(bl1.x));
            mma_tf32(acc[1], a0, a1, a2, a3, __float_as_uint(bl0.y), __float_as_uint(bl1.y));
            mma_tf32(acc[2], a0, a1, a2, a3, __float_as_uint(bl0.z), __float_as_uint(bl1.z));
            mma_tf32(acc[3], a0, a1, a2, a3, __float_as_uint(bl0.w), __float_as_uint(bl1.w));
            mma_tf32(acc[4], a0, a1, a2, a3, __float_as_uint(bh0.x), __float_as_uint(bh1.x));
            mma_tf32(acc[5], a0, a1, a2, a3, __float_as_uint(bh0.y), __float_as_uint(bh1.y));
            mma_tf32(acc[6], a0, a1, a2, a3, __float_as_uint(bh0.z), __float_as_uint(bh1.z));
            mma_tf32(acc[7], a0, a1, a2, a3, __float_as_uint(bh0.w), __float_as_uint(bh1.w));
        }
    }

    // ---- epilogue: merge the two j-half partials -------------------------
    __syncthreads();                       // all tiles done; stage smem free
    float* eS    = (float*)smem;           // 64 x 66 floats (16.9 KB)
    float* lsumS = (float*)(smem + 64 * 66 * 4);  // 2 x 64 floats

    sum0 += __shfl_xor_sync(0xFFFFFFFFu, sum0, 1);
    sum0 += __shfl_xor_sync(0xFFFFFFFFu, sum0, 2);
    sum1 += __shfl_xor_sync(0xFFFFFFFFu, sum1, 1);
    sum1 += __shfl_xor_sync(0xFFFFFFFFu, sum1, 2);
    if (tig == 0) {
        lsumS[jh * 64 + r0l] = sum0;
        lsumS[jh * 64 + r1l] = sum1;
    }

    if (jh == 0) {
        #pragma unroll
        for (int n = 0; n < 8; ++n) {
            *(float2*)&eS[r0l * 66 + n * 8 + tig * 2] = make_float2(acc[n][0], acc[n][1]);
            *(float2*)&eS[r1l * 66 + n * 8 + tig * 2] = make_float2(acc[n][2], acc[n][3]);
        }
    }
    __syncthreads();
    if (jh == 1) {
        #pragma unroll
        for (int n = 0; n < 8; ++n) {
            int f = n * 8 + tig * 2;
            float2 p0 = *(const float2*)&eS[r0l * 66 + f];
            float2 p1 = *(const float2*)&eS[r1l * 66 + f];
            *(float2*)&g_part[qh][(size_t)(i0 + r0l) * F_OUT + f] =
                make_float2(acc[n][0] + p0.x, acc[n][1] + p0.y);
            *(float2*)&g_part[qh][(size_t)(i0 + r1l) * F_OUT + f] =
                make_float2(acc[n][2] + p1.x, acc[n][3] + p1.y);
        }
        if (tig == 0) {
            g_lpart[qh][i0 + r0l] = lsumS[r0l] + lsumS[64 + r0l];
            g_lpart[qh][i0 + r1l] = lsumS[r1l] + lsumS[64 + r1l];
        }
    }
}

// ---------------------------------------------------------------------------
// Kernel D: out = (sum_q part_q) / (sum_q l_q) + bias
// ---------------------------------------------------------------------------
__global__ __launch_bounds__(256) void combine_kernel(const float* __restrict__ bias,
                                                      float* __restrict__ out) {
    int idx = blockIdx.x * 256 + threadIdx.x;    // 8192*16 float4 slots
    int i  = idx >> 4;
    int fq = idx & 15;
    size_t off = (size_t)i * F_OUT + fq * 4;

    float4 p = *(const float4*)&g_part[0][off];
    float  l = g_lpart[0][i];
    #pragma unroll
    for (int q = 1; q < JSPLIT; ++q) {
        float4 pq = *(const float4*)&g_part[q][off];
        p.x += pq.x; p.y += pq.y; p.z += pq.z; p.w += pq.w;
        l += g_lpart[q][i];
    }
    float inv = 1.0f / l;
    float4 bz = *(const float4*)&bias[fq * 4];
    float4 r;
    r.x = p.x * inv + bz.x;
    r.y = p.y * inv + bz.y;
    r.z = p.z * inv + bz.z;
    r.w = p.w * inv + bz.w;
    *(float4*)&out[off] = r;
}

// ---------------------------------------------------------------------------
extern "C" void kernel_launch(void* const* d_in, const int* in_sizes, int n_in,
                              void* d_out, int out_size) {
    const float* x    = (const float*)d_in[0];
    const int*   adj  = (const int*)  d_in[1];
    const float* W    = (const float*)d_in[2];
    const float* bias = (const float*)d_in[3];
    const float* A    = (const float*)d_in[4];
    float*       out  = (float*)d_out;

    cudaFuncSetAttribute(attn_kernel,
                         cudaFuncAttributeMaxDynamicSharedMemorySize, SMEM_SZ);

    wh_kernel   <<<N_NODES / 64, 256>>>(x, W);
    s_kernel    <<<N_NODES / 8,  256>>>(A);
    s2max_kernel<<<1, 1024>>>();
    attn_kernel <<<(N_NODES / ROWS_B) * JSPLIT, 256, SMEM_SZ>>>(adj);
    combine_kernel<<<N_NODES * 16 / 256, 256>>>(bias, out);
}

// round 12
// speedup vs baseline: 1.1850x; 1.1850x over previous
#include <cuda_runtime.h>
#include <cuda_fp16.h>
#include <math.h>
#include <stdint.h>

#define N_NODES 8192
#define F_IN    512
#define F_OUT   64
#define ALPHA   0.2f

#define TJ      32
#define JSPLIT  8
#define JQ      (N_NODES / JSPLIT)   // 1024
#define TILES_B (JQ / TJ)            // 32 tiles per block
#define ROWS_B  64                   // i-rows per block

// SMEM stage layout (bytes)
#define ADJ_STRIDE 144               // 36 ints per adj row (32 data + pad)
#define WHB2_OFF   9216              // after 64 adj rows
#define WHB2_STR   272               // 16 chunks of 16B + 16B pad (17*16, odd chunk-stride)
#define S2T_OFF    13568             // 9216 + 16*272
#define STAGE      13696             // + 128B s2
#define RING       4
#define SMEM_SZ    (STAGE * RING)    // 54784 (x4 blocks = 214KB/SM)

// Scratch (no allocations allowed anywhere)
__device__ float   g_Wh  [N_NODES * F_OUT];
// j-pair-packed fp16 Wh: entry [jp][g*8+n] = (Wh[2jp][n*8+g], Wh[2jp+1][n*8+g])
__device__ __half2 g_WhB2[(N_NODES / 2) * F_OUT];
__device__ float   g_s1  [N_NODES];
__device__ float   g_s2  [N_NODES];
__device__ float   g_s2max;
__device__ float   g_part [JSPLIT][N_NODES * F_OUT];
__device__ float   g_lpart[JSPLIT][N_NODES];

// ---- helpers ---------------------------------------------------------------
__device__ __forceinline__ uint32_t smem_u32(const void* p) {
    uint32_t r;
    asm("{ .reg .u64 t; cvta.to.shared.u64 t, %1; cvt.u32.u64 %0, t; }"
        : "=r"(r) : "l"(p));
    return r;
}
__device__ __forceinline__ void cp_async16(uint32_t dst, const void* src) {
    asm volatile("cp.async.cg.shared.global [%0], [%1], 16;"
                 :: "r"(dst), "l"(src) : "memory");
}
__device__ __forceinline__ void cp_commit() {
    asm volatile("cp.async.commit_group;" ::: "memory");
}
__device__ __forceinline__ void cp_wait1() {
    asm volatile("cp.async.wait_group 1;" ::: "memory");
}
__device__ __forceinline__ void cp_wait2() {
    asm volatile("cp.async.wait_group 2;" ::: "memory");
}
__device__ __forceinline__ uint32_t to_tf32(float x) {
    uint32_t r;
    asm("cvt.rna.tf32.f32 %0, %1;" : "=r"(r) : "f"(x));
    return r;
}
// pack two f32 into f16x2: lo -> low half, hi -> high half
__device__ __forceinline__ uint32_t f16x2(float lo, float hi) {
    uint32_t r;
    asm("cvt.rn.f16x2.f32 %0, %1, %2;" : "=r"(r) : "f"(hi), "f"(lo));
    return r;
}
__device__ __forceinline__ void mma_tf32(float* c, uint32_t a0, uint32_t a1,
                                         uint32_t a2, uint32_t a3,
                                         uint32_t b0, uint32_t b1) {
    asm volatile(
        "mma.sync.aligned.m16n8k8.row.col.f32.tf32.tf32.f32 "
        "{%0,%1,%2,%3}, {%4,%5,%6,%7}, {%8,%9}, {%0,%1,%2,%3};"
        : "+f"(c[0]), "+f"(c[1]), "+f"(c[2]), "+f"(c[3])
        : "r"(a0), "r"(a1), "r"(a2), "r"(a3), "r"(b0), "r"(b1));
}
__device__ __forceinline__ void mma_f16(float* c, uint32_t a0, uint32_t a1,
                                        uint32_t a2, uint32_t a3,
                                        uint32_t b0, uint32_t b1) {
    asm volatile(
        "mma.sync.aligned.m16n8k16.row.col.f32.f16.f16.f32 "
        "{%0,%1,%2,%3}, {%4,%5,%6,%7}, {%8,%9}, {%0,%1,%2,%3};"
        : "+f"(c[0]), "+f"(c[1]), "+f"(c[2]), "+f"(c[3])
        : "r"(a0), "r"(a1), "r"(a2), "r"(a3), "r"(b0), "r"(b1));
}

// ---------------------------------------------------------------------------
// Kernel A: Wh = x @ W via tf32 mma.sync (fp32 out). K=512.
// ---------------------------------------------------------------------------
#define XS_STR 36
#define WS_STR 72
__global__ __launch_bounds__(256) void wh_kernel(const float* __restrict__ x,
                                                 const float* __restrict__ W) {
    __shared__ __align__(16) float xs[2][64 * XS_STR];
    __shared__ __align__(16) float ws[2][32 * WS_STR];

    const int tid  = threadIdx.x;
    const int w    = tid >> 5, lane = tid & 31;
    const int wr   = w & 3,    wc   = w >> 2;
    const int g    = lane >> 2, tig = lane & 3;
    const int r0   = blockIdx.x * 64;
    const int r0l  = wr * 16 + g;
    const int r1l  = r0l + 8;

    const uint32_t xs0 = smem_u32(xs);
    const uint32_t ws0 = smem_u32(ws);

    auto prefetch = [&](int s) {
        if (s < 16) {
            int b = s & 1;
            int k0 = s * 32;
            #pragma unroll
            for (int c = tid; c < 512; c += 256) {     // x: 64 rows x 32 k
                int r = c >> 3, q = c & 7;
                cp_async16(xs0 + (b * 64 * XS_STR + r * XS_STR) * 4 + q * 16,
                           x + (size_t)(r0 + r) * F_IN + k0 + q * 4);
            }
            #pragma unroll
            for (int c = tid; c < 512; c += 256) {     // W: 32 k x 64 f
                int r = c >> 4, q = c & 15;
                cp_async16(ws0 + (b * 32 * WS_STR + r * WS_STR) * 4 + q * 16,
                           W + (size_t)(k0 + r) * F_OUT + q * 4);
            }
        }
        cp_commit();
    };

    float acc[4][4] = {};
    prefetch(0);

    for (int s = 0; s < 16; ++s) {
        prefetch(s + 1);
        cp_wait1();
        __syncthreads();

        const float* xp = &xs[s & 1][0];
        const float* wp = &ws[s & 1][0];

        #pragma unroll
        for (int kc = 0; kc < 4; ++kc) {
            uint32_t a0 = to_tf32(xp[r0l * XS_STR + kc * 8 + tig]);
            uint32_t a1 = to_tf32(xp[r1l * XS_STR + kc * 8 + tig]);
            uint32_t a2 = to_tf32(xp[r0l * XS_STR + kc * 8 + tig + 4]);
            uint32_t a3 = to_tf32(xp[r1l * XS_STR + kc * 8 + tig + 4]);
            #pragma unroll
            for (int n = 0; n < 4; ++n) {
                int f = wc * 32 + n * 8 + g;
                uint32_t b0 = to_tf32(wp[(kc * 8 + tig)     * WS_STR + f]);
                uint32_t b1 = to_tf32(wp[(kc * 8 + tig + 4) * WS_STR + f]);
                mma_tf32(acc[n], a0, a1, a2, a3, b0, b1);
            }
        }
        __syncthreads();
    }

    #pragma unroll
    for (int n = 0; n < 4; ++n) {
        int f = wc * 32 + n * 8 + tig * 2;
        *(float2*)&g_Wh[(size_t)(r0 + r0l) * F_OUT + f] = make_float2(acc[n][0], acc[n][1]);
        *(float2*)&g_Wh[(size_t)(r0 + r1l) * F_OUT + f] = make_float2(acc[n][2], acc[n][3]);
    }
}

// ---------------------------------------------------------------------------
// Kernel A2: g_WhB2[jp][g*8+n] = half2(Wh[2jp][n*8+g], Wh[2jp+1][n*8+g])
// ---------------------------------------------------------------------------
__global__ __launch_bounds__(256) void packwh_kernel() {
    int idx = blockIdx.x * 256 + threadIdx.x;   // 256K entries
    int jp = idx >> 6;
    int fp = idx & 63;
    int g = fp >> 3, n = fp & 7;
    int f = n * 8 + g;
    float lo = g_Wh[(size_t)(2 * jp)     * F_OUT + f];
    float hi = g_Wh[(size_t)(2 * jp + 1) * F_OUT + f];
    g_WhB2[idx] = __floats2half2_rn(lo, hi);
}

// ---------------------------------------------------------------------------
// Kernel B: s1 = Wh @ a1, s2 = Wh @ a2
// ---------------------------------------------------------------------------
__global__ __launch_bounds__(256) void s_kernel(const float* __restrict__ A) {
    const int row  = blockIdx.x * 8 + (threadIdx.x >> 5);
    const int lane = threadIdx.x & 31;
    float w0 = g_Wh[row * F_OUT + lane];
    float w1 = g_Wh[row * F_OUT + lane + 32];
    float v1 = w0 * A[lane]         + w1 * A[lane + 32];
    float v2 = w0 * A[F_OUT + lane] + w1 * A[F_OUT + lane + 32];
    #pragma unroll
    for (int off = 16; off; off >>= 1) {
        v1 += __shfl_xor_sync(0xFFFFFFFFu, v1, off);
        v2 += __shfl_xor_sync(0xFFFFFFFFu, v2, off);
    }
    if (lane == 0) { g_s1[row] = v1; g_s2[row] = v2; }
}

// ---------------------------------------------------------------------------
// Kernel B2: g_s2max = max(g_s2)
// ---------------------------------------------------------------------------
__global__ __launch_bounds__(1024) void s2max_kernel() {
    __shared__ float sm[32];
    const int tid = threadIdx.x;
    float m = -INFINITY;
    for (int i = tid; i < N_NODES; i += 1024) m = fmaxf(m, g_s2[i]);
    #pragma unroll
    for (int off = 16; off; off >>= 1)
        m = fmaxf(m, __shfl_xor_sync(0xFFFFFFFFu, m, off));
    if ((tid & 31) == 0) sm[tid >> 5] = m;
    __syncthreads();
    if (tid < 32) {
        m = sm[tid];
        #pragma unroll
        for (int off = 16; off; off >>= 1)
            m = fmaxf(m, __shfl_xor_sync(0xFFFFFFFFu, m, off));
        if (tid == 0) g_s2max = m;
    }
}

// ---------------------------------------------------------------------------
// Kernel C: fused attention via mma.sync fp16 (m16n8k16).
// grid = 128 i-blocks x 8 j-slices = 1024 blocks, 4 blocks/SM, ring 4.
// 8 warps = 4 row-tiles (wr) x 2 j-halves (jh). Each warp: 16 rows x 16 j
// (one k16 chunk) x 64 f.
// WhB2 stage rows use stride 272 (odd 16B-chunk count) + chunk swizzle
// p = (c + (jp&2)) & 15  -> conflict-free LDS.128 in every phase.
// ---------------------------------------------------------------------------
__global__ __launch_bounds__(256, 4) void attn_kernel(const int* __restrict__ adj) {
    extern __shared__ __align__(1024) char smem[];
    const int tid  = threadIdx.x;
    const int w    = tid >> 5, lane = tid & 31;
    const int wr   = w & 3,    jh   = w >> 2;
    const int g    = lane >> 2, tig = lane & 3;
    const int i0   = (blockIdx.x >> 3) * ROWS_B;
    const int qh   = blockIdx.x & 7;
    const int j0b  = qh * JQ;
    const int r0l  = wr * 16 + g;
    const int r1l  = r0l + 8;

    const uint32_t sb = smem_u32(smem);

    // prefetch-thread invariants
    const int pr  = tid >> 3, pq8 = tid & 7;      // adj: row, 16B-chunk
    const int wr_ = tid >> 4, wq  = tid & 15;     // WhB2: jp row, src chunk
    const uint32_t adj_dst0 = sb + pr * ADJ_STRIDE + pq8 * 16;
    const uint32_t adj_dst1 = adj_dst0 + 32 * ADJ_STRIDE;
    const uint32_t wh_dst   = sb + WHB2_OFF + wr_ * WHB2_STR
                              + (((wq + (wr_ & 2)) & 15) * 16);   // swizzled pos
    const int      a_row0   = r0l * ADJ_STRIDE;
    const int      a_row1   = r1l * ADJ_STRIDE;

    const int* adj_src0 = adj + (size_t)(i0 + pr)      * N_NODES + j0b + pq8 * 4;
    const int* adj_src1 = adj + (size_t)(i0 + pr + 32) * N_NODES + j0b + pq8 * 4;
    const char* wh_src  = (const char*)g_WhB2 + ((size_t)(j0b >> 1) + wr_) * 256 + wq * 16;
    const float* s2_src = g_s2 + j0b + (tid & 7) * 4;

    auto prefetch = [&](int t) {
        if (t < TILES_B) {
            uint32_t base = (uint32_t)((t & 3) * STAGE);
            int joff = t * TJ;
            cp_async16(adj_dst0 + base, adj_src0 + joff);
            cp_async16(adj_dst1 + base, adj_src1 + joff);
            cp_async16(wh_dst + base, wh_src + (size_t)t * 4096);
            if (tid < 8)
                cp_async16(sb + S2T_OFF + base + tid * 16, s2_src + joff);
        }
        cp_commit();
    };

    const float s1_0 = g_s1[i0 + r0l];
    const float s1_1 = g_s1[i0 + r1l];
    const float s2m  = g_s2max;
    const float m0 = fmaxf(s1_0 + s2m, ALPHA * (s1_0 + s2m));
    const float m1 = fmaxf(s1_1 + s2m, ALPHA * (s1_1 + s2m));

    float acc[8][4] = {};
    float sum0 = 0.f, sum1 = 0.f;

    prefetch(0); prefetch(1); prefetch(2);

    const int jA  = jh * 16 + 2 * tig;       // local j of a0 pair
    const int jB  = jA + 8;                  // local j of a2 pair
    const int jp0 = jh * 8 + tig;            // jp row for b0
    const int jp1 = jp0 + 4;                 // jp row for b1
    // swizzled chunk byte-offsets within a WhB2 row (d = jp&2 same for jp0/jp1)
    const int d   = tig & 2;
    const uint32_t pLo = (uint32_t)(((2 * g + d) & 15) * 16);
    const uint32_t pHi = (uint32_t)(((2 * g + 1 + d) & 15) * 16);
    const uint32_t bOff0 = (uint32_t)(WHB2_OFF + jp0 * WHB2_STR);
    const uint32_t bOff1 = (uint32_t)(WHB2_OFF + jp1 * WHB2_STR);

    for (int t = 0; t < TILES_B; ++t) {
        cp_wait2();
        __syncthreads();
        prefetch(t + 3);     // slot (t-1)&3; its reads finished at the barrier

        const char* base = smem + (t & 3) * STAGE;

        // s2 pairs (staged per tile)
        float2 s2a = *(const float2*)(base + S2T_OFF + jA * 4);
        float2 s2b = *(const float2*)(base + S2T_OFF + jB * 4);
        // adj pairs
        int2 A0a = *(const int2*)(base + a_row0 + jA * 4);
        int2 A0b = *(const int2*)(base + a_row0 + jB * 4);
        int2 A1a = *(const int2*)(base + a_row1 + jA * 4);
        int2 A1b = *(const int2*)(base + a_row1 + jB * 4);

        // 8 attention weights -> 4 packed f16x2 A-regs
        float t00 = s1_0 + s2a.x, t01 = s1_0 + s2a.y;
        float t02 = s1_0 + s2b.x, t03 = s1_0 + s2b.y;
        float t10 = s1_1 + s2a.x, t11 = s1_1 + s2a.y;
        float t12 = s1_1 + s2b.x, t13 = s1_1 + s2b.y;
        float w00 = (A0a.x > 0) ? __expf(fmaxf(t00, ALPHA * t00) - m0) : 0.f;
        float w01 = (A0a.y > 0) ? __expf(fmaxf(t01, ALPHA * t01) - m0) : 0.f;
        float w02 = (A0b.x > 0) ? __expf(fmaxf(t02, ALPHA * t02) - m0) : 0.f;
        float w03 = (A0b.y > 0) ? __expf(fmaxf(t03, ALPHA * t03) - m0) : 0.f;
        float w10 = (A1a.x > 0) ? __expf(fmaxf(t10, ALPHA * t10) - m1) : 0.f;
        float w11 = (A1a.y > 0) ? __expf(fmaxf(t11, ALPHA * t11) - m1) : 0.f;
        float w12 = (A1b.x > 0) ? __expf(fmaxf(t12, ALPHA * t12) - m1) : 0.f;
        float w13 = (A1b.y > 0) ? __expf(fmaxf(t13, ALPHA * t13) - m1) : 0.f;
        sum0 += (w00 + w01) + (w02 + w03);
        sum1 += (w10 + w11) + (w12 + w13);
        uint32_t a0 = f16x2(w00, w01);
        uint32_t a1 = f16x2(w10, w11);
        uint32_t a2 = f16x2(w02, w03);
        uint32_t a3 = f16x2(w12, w13);

        // B fragments: 4 x LDS.128 (conflict-free via swizzle)
        uint4 bl0 = *(const uint4*)(base + bOff0 + pLo);
        uint4 bh0 = *(const uint4*)(base + bOff0 + pHi);
        uint4 bl1 = *(const uint4*)(base + bOff1 + pLo);
        uint4 bh1 = *(const uint4*)(base + bOff1 + pHi);

        mma_f16(acc[0], a0, a1, a2, a3, bl0.x, bl1.x);
        mma_f16(acc[1], a0, a1, a2, a3, bl0.y, bl1.y);
        mma_f16(acc[2], a0, a1, a2, a3, bl0.z, bl1.z);
        mma_f16(acc[3], a0, a1, a2, a3, bl0.w, bl1.w);
        mma_f16(acc[4], a0, a1, a2, a3, bh0.x, bh1.x);
        mma_f16(acc[5], a0, a1, a2, a3, bh0.y, bh1.y);
        mma_f16(acc[6], a0, a1, a2, a3, bh0.z, bh1.z);
        mma_f16(acc[7], a0, a1, a2, a3, bh0.w, bh1.w);
    }

    // ---- epilogue: merge the two j-half partials -------------------------
    __syncthreads();                       // all tiles done; stage smem free
    float* eS    = (float*)smem;           // 64 x 66 floats (16.9 KB)
    float* lsumS = (float*)(smem + 64 * 66 * 4);  // 2 x 64 floats

    sum0 += __shfl_xor_sync(0xFFFFFFFFu, sum0, 1);
    sum0 += __shfl_xor_sync(0xFFFFFFFFu, sum0, 2);
    sum1 += __shfl_xor_sync(0xFFFFFFFFu, sum1, 1);
    sum1 += __shfl_xor_sync(0xFFFFFFFFu, sum1, 2);
    if (tig == 0) {
        lsumS[jh * 64 + r0l] = sum0;
        lsumS[jh * 64 + r1l] = sum1;
    }

    if (jh == 0) {
        #pragma unroll
        for (int n = 0; n < 8; ++n) {
            *(float2*)&eS[r0l * 66 + n * 8 + tig * 2] = make_float2(acc[n][0], acc[n][1]);
            *(float2*)&eS[r1l * 66 + n * 8 + tig * 2] = make_float2(acc[n][2], acc[n][3]);
        }
    }
    __syncthreads();
    if (jh == 1) {
        #pragma unroll
        for (int n = 0; n < 8; ++n) {
            int f = n * 8 + tig * 2;
            float2 p0 = *(const float2*)&eS[r0l * 66 + f];
            float2 p1 = *(const float2*)&eS[r1l * 66 + f];
            *(float2*)&g_part[qh][(size_t)(i0 + r0l) * F_OUT + f] =
                make_float2(acc[n][0] + p0.x, acc[n][1] + p0.y);
            *(float2*)&g_part[qh][(size_t)(i0 + r1l) * F_OUT + f] =
                make_float2(acc[n][2] + p1.x, acc[n][3] + p1.y);
        }
        if (tig == 0) {
            g_lpart[qh][i0 + r0l] = lsumS[r0l] + lsumS[64 + r0l];
            g_lpart[qh][i0 + r1l] = lsumS[r1l] + lsumS[64 + r1l];
        }
    }
}

// ---------------------------------------------------------------------------
// Kernel D: out = (sum_q part_q) / (sum_q l_q) + bias
// ---------------------------------------------------------------------------
__global__ __launch_bounds__(256) void combine_kernel(const float* __restrict__ bias,
                                                      float* __restrict__ out) {
    int idx = blockIdx.x * 256 + threadIdx.x;    // 8192*16 float4 slots
    int i  = idx >> 4;
    int fq = idx & 15;
    size_t off = (size_t)i * F_OUT + fq * 4;

    float4 p = *(const float4*)&g_part[0][off];
    float  l = g_lpart[0][i];
    #pragma unroll
    for (int q = 1; q < JSPLIT; ++q) {
        float4 pq = *(const float4*)&g_part[q][off];
        p.x += pq.x; p.y += pq.y; p.z += pq.z; p.w += pq.w;
        l += g_lpart[q][i];
    }
    float inv = 1.0f / l;
    float4 bz = *(const float4*)&bias[fq * 4];
    float4 r;
    r.x = p.x * inv + bz.x;
    r.y = p.y * inv + bz.y;
    r.z = p.z * inv + bz.z;
    r.w = p.w * inv + bz.w;
    *(float4*)&out[off] = r;
}

// ---------------------------------------------------------------------------
extern "C" void kernel_launch(void* const* d_in, const int* in_sizes, int n_in,
                              void* d_out, int out_size) {
    const float* x    = (const float*)d_in[0];
    const int*   adj  = (const int*)  d_in[1];
    const float* W    = (const float*)d_in[2];
    const float* bias = (const float*)d_in[3];
    const float* A    = (const float*)d_in[4];
    float*       out  = (float*)d_out;

    cudaFuncSetAttribute(attn_kernel,
                         cudaFuncAttributeMaxDynamicSharedMemorySize, SMEM_SZ);

    wh_kernel    <<<N_NODES / 64, 256>>>(x, W);
    packwh_kernel<<<(N_NODES / 2) * F_OUT / 256, 256>>>();
    s_kernel     <<<N_NODES / 8,  256>>>(A);
    s2max_kernel <<<1, 1024>>>();
    attn_kernel  <<<(N_NODES / ROWS_B) * JSPLIT, 256, SMEM_SZ>>>(adj);
    combine_kernel<<<N_NODES * 16 / 256, 256>>>(bias, out);
}

// round 13
// speedup vs baseline: 1.2498x; 1.0547x over previous
#include <cuda_runtime.h>
#include <cuda_fp16.h>
#include <math.h>
#include <stdint.h>

#define N_NODES 8192
#define F_IN    512
#define F_OUT   64
#define ALPHA   0.2f

#define TJ      32
#define JSPLIT  8
#define JQ      (N_NODES / JSPLIT)   // 1024
#define TILES_B (JQ / TJ)            // 32 tiles per block
#define ROWS_B  64                   // i-rows per block

// SMEM stage layout (bytes)
#define ADJ_STRIDE 144               // 36 ints per adj row (32 data + pad)
#define WHB2_OFF   9216              // after 64 adj rows
#define WHB2_STR   272               // 16 chunks of 16B + 16B pad (17*16)
#define S2T_OFF    13568             // 9216 + 16*272
#define STAGE      13696             // + 128B s2
#define RING       4
#define SMEM_SZ    (STAGE * RING)    // 54784 (x4 blocks = 214KB/SM)

// Scratch (no allocations allowed anywhere)
__device__ float    g_Wh  [N_NODES * F_OUT];
// j-pair-packed fp16 Wh: entry [jp][g2*8+n2] = (Wh[2jp][n2*8+g2], Wh[2jp+1][n2*8+g2])
__device__ __half2  g_WhB2[(N_NODES / 2) * F_OUT];
__device__ float    g_s1  [N_NODES];
__device__ float    g_s2  [N_NODES];
__device__ unsigned g_s2max_bits;    // monotone float key; init by wh block 0
__device__ float    g_part [JSPLIT][N_NODES * F_OUT];
__device__ float    g_lpart[JSPLIT][N_NODES];

// ---- helpers ---------------------------------------------------------------
__device__ __forceinline__ uint32_t smem_u32(const void* p) {
    uint32_t r;
    asm("{ .reg .u64 t; cvta.to.shared.u64 t, %1; cvt.u32.u64 %0, t; }"
        : "=r"(r) : "l"(p));
    return r;
}
__device__ __forceinline__ void cp_async16(uint32_t dst, const void* src) {
    asm volatile("cp.async.cg.shared.global [%0], [%1], 16;"
                 :: "r"(dst), "l"(src) : "memory");
}
__device__ __forceinline__ void cp_commit() {
    asm volatile("cp.async.commit_group;" ::: "memory");
}
__device__ __forceinline__ void cp_wait1() {
    asm volatile("cp.async.wait_group 1;" ::: "memory");
}
__device__ __forceinline__ void cp_wait2() {
    asm volatile("cp.async.wait_group 2;" ::: "memory");
}
__device__ __forceinline__ uint32_t to_tf32(float x) {
    uint32_t r;
    asm("cvt.rna.tf32.f32 %0, %1;" : "=r"(r) : "f"(x));
    return r;
}
// pack two f32 into f16x2: lo -> low half, hi -> high half
__device__ __forceinline__ uint32_t f16x2(float lo, float hi) {
    uint32_t r;
    asm("cvt.rn.f16x2.f32 %0, %1, %2;" : "=r"(r) : "f"(hi), "f"(lo));
    return r;
}
// monotone float <-> unsigned key (unsigned order == float order)
__device__ __forceinline__ unsigned f2key(float f) {
    unsigned b = __float_as_uint(f);
    return (b & 0x80000000u) ? ~b : (b | 0x80000000u);
}
__device__ __forceinline__ float key2f(unsigned k) {
    return __uint_as_float((k & 0x80000000u) ? (k ^ 0x80000000u) : ~k);
}
__device__ __forceinline__ void mma_tf32(float* c, uint32_t a0, uint32_t a1,
                                         uint32_t a2, uint32_t a3,
                                         uint32_t b0, uint32_t b1) {
    asm volatile(
        "mma.sync.aligned.m16n8k8.row.col.f32.tf32.tf32.f32 "
        "{%0,%1,%2,%3}, {%4,%5,%6,%7}, {%8,%9}, {%0,%1,%2,%3};"
        : "+f"(c[0]), "+f"(c[1]), "+f"(c[2]), "+f"(c[3])
        : "r"(a0), "r"(a1), "r"(a2), "r"(a3), "r"(b0), "r"(b1));
}
__device__ __forceinline__ void mma_f16(float* c, uint32_t a0, uint32_t a1,
                                        uint32_t a2, uint32_t a3,
                                        uint32_t b0, uint32_t b1) {
    asm volatile(
        "mma.sync.aligned.m16n8k16.row.col.f32.f16.f16.f32 "
        "{%0,%1,%2,%3}, {%4,%5,%6,%7}, {%8,%9}, {%0,%1,%2,%3};"
        : "+f"(c[0]), "+f"(c[1]), "+f"(c[2]), "+f"(c[3])
        : "r"(a0), "r"(a1), "r"(a2), "r"(a3), "r"(b0), "r"(b1));
}

// ---------------------------------------------------------------------------
// Kernel A: Wh = x @ W via tf32 mma.sync (fp32 out). K=512.
// Epilogue ALSO writes g_WhB2 (fp16 packed) via lane-pair shuffles, and
// block 0 initializes g_s2max_bits.
// ---------------------------------------------------------------------------
#define XS_STR 36
#define WS_STR 72
__global__ __launch_bounds__(256) void wh_kernel(const float* __restrict__ x,
                                                 const float* __restrict__ W) {
    __shared__ __align__(16) float xs[2][64 * XS_STR];
    __shared__ __align__(16) float ws[2][32 * WS_STR];

    const int tid  = threadIdx.x;
    const int w    = tid >> 5, lane = tid & 31;
    const int wr   = w & 3,    wc   = w >> 2;
    const int g    = lane >> 2, tig = lane & 3;
    const int r0   = blockIdx.x * 64;
    const int r0l  = wr * 16 + g;
    const int r1l  = r0l + 8;

    if (blockIdx.x == 0 && tid == 0) g_s2max_bits = 0u;   // key of -most

    const uint32_t xs0 = smem_u32(xs);
    const uint32_t ws0 = smem_u32(ws);

    auto prefetch = [&](int s) {
        if (s < 16) {
            int b = s & 1;
            int k0 = s * 32;
            #pragma unroll
            for (int c = tid; c < 512; c += 256) {     // x: 64 rows x 32 k
                int r = c >> 3, q = c & 7;
                cp_async16(xs0 + (b * 64 * XS_STR + r * XS_STR) * 4 + q * 16,
                           x + (size_t)(r0 + r) * F_IN + k0 + q * 4);
            }
            #pragma unroll
            for (int c = tid; c < 512; c += 256) {     // W: 32 k x 64 f
                int r = c >> 4, q = c & 15;
                cp_async16(ws0 + (b * 32 * WS_STR + r * WS_STR) * 4 + q * 16,
                           W + (size_t)(k0 + r) * F_OUT + q * 4);
            }
        }
        cp_commit();
    };

    float acc[4][4] = {};
    prefetch(0);

    for (int s = 0; s < 16; ++s) {
        prefetch(s + 1);
        cp_wait1();
        __syncthreads();

        const float* xp = &xs[s & 1][0];
        const float* wp = &ws[s & 1][0];

        #pragma unroll
        for (int kc = 0; kc < 4; ++kc) {
            uint32_t a0 = to_tf32(xp[r0l * XS_STR + kc * 8 + tig]);
            uint32_t a1 = to_tf32(xp[r1l * XS_STR + kc * 8 + tig]);
            uint32_t a2 = to_tf32(xp[r0l * XS_STR + kc * 8 + tig + 4]);
            uint32_t a3 = to_tf32(xp[r1l * XS_STR + kc * 8 + tig + 4]);
            #pragma unroll
            for (int n = 0; n < 4; ++n) {
                int f = wc * 32 + n * 8 + g;
                uint32_t b0 = to_tf32(wp[(kc * 8 + tig)     * WS_STR + f]);
                uint32_t b1 = to_tf32(wp[(kc * 8 + tig + 4) * WS_STR + f]);
                mma_tf32(acc[n], a0, a1, a2, a3, b0, b1);
            }
        }
        __syncthreads();
    }

    // fp32 Wh stores
    #pragma unroll
    for (int n = 0; n < 4; ++n) {
        int f = wc * 32 + n * 8 + tig * 2;
        *(float2*)&g_Wh[(size_t)(r0 + r0l) * F_OUT + f] = make_float2(acc[n][0], acc[n][1]);
        *(float2*)&g_Wh[(size_t)(r0 + r1l) * F_OUT + f] = make_float2(acc[n][2], acc[n][3]);
    }

    // fused fp16 pack: even-g lanes pair with lane+4 (row r0l+1 / r1l+1)
    {
        float pacc[4][4];
        #pragma unroll
        for (int n = 0; n < 4; ++n)
            #pragma unroll
            for (int q = 0; q < 4; ++q)
                pacc[n][q] = __shfl_down_sync(0xFFFFFFFFu, acc[n][q], 4);

        if ((g & 1) == 0) {
            int jp0 = (r0 + r0l) >> 1;       // rows (r0l, r0l+1)
            int jp1 = jp0 + 4;               // rows (r1l, r1l+1)
            uint32_t pk[4][4];               // [pair(lo/hi f) x jp][n]
            #pragma unroll
            for (int n = 0; n < 4; ++n) {
                pk[0][n] = f16x2(acc[n][0], pacc[n][0]);   // jp0, f
                pk[1][n] = f16x2(acc[n][1], pacc[n][1]);   // jp0, f+1
                pk[2][n] = f16x2(acc[n][2], pacc[n][2]);   // jp1, f
                pk[3][n] = f16x2(acc[n][3], pacc[n][3]);   // jp1, f+1
            }
            int c0 = tig * 16 + wc * 4;      // index of (f) block in WhB2 row
            *(uint4*)&g_WhB2[(size_t)jp0 * F_OUT + c0]     = *(uint4*)pk[0];
            *(uint4*)&g_WhB2[(size_t)jp0 * F_OUT + c0 + 8] = *(uint4*)pk[1];
            *(uint4*)&g_WhB2[(size_t)jp1 * F_OUT + c0]     = *(uint4*)pk[2];
            *(uint4*)&g_WhB2[(size_t)jp1 * F_OUT + c0 + 8] = *(uint4*)pk[3];
        }
    }
}

// ---------------------------------------------------------------------------
// Kernel B: s1 = Wh @ a1, s2 = Wh @ a2 ; fused global max(s2) via atomicMax
// ---------------------------------------------------------------------------
__global__ __launch_bounds__(256) void s_kernel(const float* __restrict__ A) {
    __shared__ float vmax[8];
    const int row  = blockIdx.x * 8 + (threadIdx.x >> 5);
    const int lane = threadIdx.x & 31;
    const int wid  = threadIdx.x >> 5;
    float w0 = g_Wh[row * F_OUT + lane];
    float w1 = g_Wh[row * F_OUT + lane + 32];
    float v1 = w0 * A[lane]         + w1 * A[lane + 32];
    float v2 = w0 * A[F_OUT + lane] + w1 * A[F_OUT + lane + 32];
    #pragma unroll
    for (int off = 16; off; off >>= 1) {
        v1 += __shfl_xor_sync(0xFFFFFFFFu, v1, off);
        v2 += __shfl_xor_sync(0xFFFFFFFFu, v2, off);
    }
    if (lane == 0) {
        g_s1[row] = v1; g_s2[row] = v2;
        vmax[wid] = v2;
    }
    __syncthreads();
    if (threadIdx.x == 0) {
        float m = vmax[0];
        #pragma unroll
        for (int i = 1; i < 8; ++i) m = fmaxf(m, vmax[i]);
        atomicMax(&g_s2max_bits, f2key(m));
    }
}

// ---------------------------------------------------------------------------
// Kernel C: fused attention via mma.sync fp16 (m16n8k16).
// grid = 128 i-blocks x 8 j-slices = 1024 blocks, 4 blocks/SM, ring 4.
// 8 warps = 4 row-tiles (wr) x 2 j-halves (jh).
// ---------------------------------------------------------------------------
__global__ __launch_bounds__(256, 4) void attn_kernel(const int* __restrict__ adj) {
    extern __shared__ __align__(1024) char smem[];
    const int tid  = threadIdx.x;
    const int w    = tid >> 5, lane = tid & 31;
    const int wr   = w & 3,    jh   = w >> 2;
    const int g    = lane >> 2, tig = lane & 3;
    const int i0   = (blockIdx.x >> 3) * ROWS_B;
    const int qh   = blockIdx.x & 7;
    const int j0b  = qh * JQ;
    const int r0l  = wr * 16 + g;
    const int r1l  = r0l + 8;

    const uint32_t sb = smem_u32(smem);

    // prefetch-thread invariants
    const int pr  = tid >> 3, pq8 = tid & 7;      // adj: row, 16B-chunk
    const int wr_ = tid >> 4, wq  = tid & 15;     // WhB2: jp row, src chunk
    const uint32_t adj_dst0 = sb + pr * ADJ_STRIDE + pq8 * 16;
    const uint32_t adj_dst1 = adj_dst0 + 32 * ADJ_STRIDE;
    const uint32_t wh_dst   = sb + WHB2_OFF + wr_ * WHB2_STR
                              + (((wq + (wr_ & 2)) & 15) * 16);   // swizzled pos
    const int      a_row0   = r0l * ADJ_STRIDE;
    const int      a_row1   = r1l * ADJ_STRIDE;

    const int* adj_src0 = adj + (size_t)(i0 + pr)      * N_NODES + j0b + pq8 * 4;
    const int* adj_src1 = adj + (size_t)(i0 + pr + 32) * N_NODES + j0b + pq8 * 4;
    const char* wh_src  = (const char*)g_WhB2 + ((size_t)(j0b >> 1) + wr_) * 256 + wq * 16;
    const float* s2_src = g_s2 + j0b + (tid & 7) * 4;

    auto prefetch = [&](int t) {
        if (t < TILES_B) {
            uint32_t base = (uint32_t)((t & 3) * STAGE);
            int joff = t * TJ;
            cp_async16(adj_dst0 + base, adj_src0 + joff);
            cp_async16(adj_dst1 + base, adj_src1 + joff);
            cp_async16(wh_dst + base, wh_src + (size_t)t * 4096);
            if (tid < 8)
                cp_async16(sb + S2T_OFF + base + tid * 16, s2_src + joff);
        }
        cp_commit();
    };

    const float s1_0 = g_s1[i0 + r0l];
    const float s1_1 = g_s1[i0 + r1l];
    const float s2m  = key2f(g_s2max_bits);
    const float m0 = fmaxf(s1_0 + s2m, ALPHA * (s1_0 + s2m));
    const float m1 = fmaxf(s1_1 + s2m, ALPHA * (s1_1 + s2m));

    float acc[8][4] = {};
    float sum0 = 0.f, sum1 = 0.f;

    prefetch(0); prefetch(1); prefetch(2);

    const int jA  = jh * 16 + 2 * tig;       // local j of a0 pair
    const int jB  = jA + 8;                  // local j of a2 pair
    const int jp0 = jh * 8 + tig;            // jp row for b0
    const int jp1 = jp0 + 4;                 // jp row for b1
    const int d   = tig & 2;
    const uint32_t pLo = (uint32_t)(((2 * g + d) & 15) * 16);
    const uint32_t pHi = (uint32_t)(((2 * g + 1 + d) & 15) * 16);
    const uint32_t bOff0 = (uint32_t)(WHB2_OFF + jp0 * WHB2_STR);
    const uint32_t bOff1 = (uint32_t)(WHB2_OFF + jp1 * WHB2_STR);

    for (int t = 0; t < TILES_B; ++t) {
        cp_wait2();
        __syncthreads();
        prefetch(t + 3);     // slot (t-1)&3; its reads finished at the barrier

        const char* base = smem + (t & 3) * STAGE;

        float2 s2a = *(const float2*)(base + S2T_OFF + jA * 4);
        float2 s2b = *(const float2*)(base + S2T_OFF + jB * 4);
        int2 A0a = *(const int2*)(base + a_row0 + jA * 4);
        int2 A0b = *(const int2*)(base + a_row0 + jB * 4);
        int2 A1a = *(const int2*)(base + a_row1 + jA * 4);
        int2 A1b = *(const int2*)(base + a_row1 + jB * 4);

        float t00 = s1_0 + s2a.x, t01 = s1_0 + s2a.y;
        float t02 = s1_0 + s2b.x, t03 = s1_0 + s2b.y;
        float t10 = s1_1 + s2a.x, t11 = s1_1 + s2a.y;
        float t12 = s1_1 + s2b.x, t13 = s1_1 + s2b.y;
        float w00 = (A0a.x > 0) ? __expf(fmaxf(t00, ALPHA * t00) - m0) : 0.f;
        float w01 = (A0a.y > 0) ? __expf(fmaxf(t01, ALPHA * t01) - m0) : 0.f;
        float w02 = (A0b.x > 0) ? __expf(fmaxf(t02, ALPHA * t02) - m0) : 0.f;
        float w03 = (A0b.y > 0) ? __expf(fmaxf(t03, ALPHA * t03) - m0) : 0.f;
        float w10 = (A1a.x > 0) ? __expf(fmaxf(t10, ALPHA * t10) - m1) : 0.f;
        float w11 = (A1a.y > 0) ? __expf(fmaxf(t11, ALPHA * t11) - m1) : 0.f;
        float w12 = (A1b.x > 0) ? __expf(fmaxf(t12, ALPHA * t12) - m1) : 0.f;
        float w13 = (A1b.y > 0) ? __expf(fmaxf(t13, ALPHA * t13) - m1) : 0.f;
        sum0 += (w00 + w01) + (w02 + w03);
        sum1 += (w10 + w11) + (w12 + w13);
        uint32_t a0 = f16x2(w00, w01);
        uint32_t a1 = f16x2(w10, w11);
        uint32_t a2 = f16x2(w02, w03);
        uint32_t a3 = f16x2(w12, w13);

        uint4 bl0 = *(const uint4*)(base + bOff0 + pLo);
        uint4 bh0 = *(const uint4*)(base + bOff0 + pHi);
        uint4 bl1 = *(const uint4*)(base + bOff1 + pLo);
        uint4 bh1 = *(const uint4*)(base + bOff1 + pHi);

        mma_f16(acc[0], a0, a1, a2, a3, bl0.x, bl1.x);
        mma_f16(acc[1], a0, a1, a2, a3, bl0.y, bl1.y);
        mma_f16(acc[2], a0, a1, a2, a3, bl0.z, bl1.z);
        mma_f16(acc[3], a0, a1, a2, a3, bl0.w, bl1.w);
        mma_f16(acc[4], a0, a1, a2, a3, bh0.x, bh1.x);
        mma_f16(acc[5], a0, a1, a2, a3, bh0.y, bh1.y);
        mma_f16(acc[6], a0, a1, a2, a3, bh0.z, bh1.z);
        mma_f16(acc[7], a0, a1, a2, a3, bh0.w, bh1.w);
    }

    // ---- epilogue: merge the two j-half partials -------------------------
    __syncthreads();                       // all tiles done; stage smem free
    float* eS    = (float*)smem;           // 64 x 66 floats (16.9 KB)
    float* lsumS = (float*)(smem + 64 * 66 * 4);  // 2 x 64 floats

    sum0 += __shfl_xor_sync(0xFFFFFFFFu, sum0, 1);
    sum0 += __shfl_xor_sync(0xFFFFFFFFu, sum0, 2);
    sum1 += __shfl_xor_sync(0xFFFFFFFFu, sum1, 1);
    sum1 += __shfl_xor_sync(0xFFFFFFFFu, sum1, 2);
    if (tig == 0) {
        lsumS[jh * 64 + r0l] = sum0;
        lsumS[jh * 64 + r1l] = sum1;
    }

    if (jh == 0) {
        #pragma unroll
        for (int n = 0; n < 8; ++n) {
            *(float2*)&eS[r0l * 66 + n * 8 + tig * 2] = make_float2(acc[n][0], acc[n][1]);
            *(float2*)&eS[r1l * 66 + n * 8 + tig * 2] = make_float2(acc[n][2], acc[n][3]);
        }
    }
    __syncthreads();
    if (jh == 1) {
        #pragma unroll
        for (int n = 0; n < 8; ++n) {
            int f = n * 8 + tig * 2;
            float2 p0 = *(const float2*)&eS[r0l * 66 + f];
            float2 p1 = *(const float2*)&eS[r1l * 66 + f];
            *(float2*)&g_part[qh][(size_t)(i0 + r0l) * F_OUT + f] =
                make_float2(acc[n][0] + p0.x, acc[n][1] + p0.y);
            *(float2*)&g_part[qh][(size_t)(i0 + r1l) * F_OUT + f] =
                make_float2(acc[n][2] + p1.x, acc[n][3] + p1.y);
        }
        if (tig == 0) {
            g_lpart[qh][i0 + r0l] = lsumS[r0l] + lsumS[64 + r0l];
            g_lpart[qh][i0 + r1l] = lsumS[r1l] + lsumS[64 + r1l];
        }
    }
}

// ---------------------------------------------------------------------------
// Kernel D: out = (sum_q part_q) / (sum_q l_q) + bias
// ---------------------------------------------------------------------------
__global__ __launch_bounds__(256) void combine_kernel(const float* __restrict__ bias,
                                                      float* __restrict__ out) {
    int idx = blockIdx.x * 256 + threadIdx.x;    // 8192*16 float4 slots
    int i  = idx >> 4;
    int fq = idx & 15;
    size_t off = (size_t)i * F_OUT + fq * 4;

    float4 p = *(const float4*)&g_part[0][off];
    float  l = g_lpart[0][i];
    #pragma unroll
    for (int q = 1; q < JSPLIT; ++q) {
        float4 pq = *(const float4*)&g_part[q][off];
        p.x += pq.x; p.y += pq.y; p.z += pq.z; p.w += pq.w;
        l += g_lpart[q][i];
    }
    float inv = 1.0f / l;
    float4 bz = *(const float4*)&bias[fq * 4];
    float4 r;
    r.x = p.x * inv + bz.x;
    r.y = p.y * inv + bz.y;
    r.z = p.z * inv + bz.z;
    r.w = p.w * inv + bz.w;
    *(float4*)&out[off] = r;
}

// ---------------------------------------------------------------------------
extern "C" void kernel_launch(void* const* d_in, const int* in_sizes, int n_in,
                              void* d_out, int out_size) {
    const float* x    = (const float*)d_in[0];
    const int*   adj  = (const int*)  d_in[1];
    const float* W    = (const float*)d_in[2];
    const float* bias = (const float*)d_in[3];
    const float* A    = (const float*)d_in[4];
    float*       out  = (float*)d_out;

    cudaFuncSetAttribute(attn_kernel,
                         cudaFuncAttributeMaxDynamicSharedMemorySize, SMEM_SZ);

    wh_kernel     <<<N_NODES / 64, 256>>>(x, W);
    s_kernel      <<<N_NODES / 8,  256>>>(A);
    attn_kernel   <<<(N_NODES / ROWS_B) * JSPLIT, 256, SMEM_SZ>>>(adj);
    combine_kernel<<<N_NODES * 16 / 256, 256>>>(bias, out);
}

// round 14
// speedup vs baseline: 1.3217x; 1.0575x over previous
#include <cuda_runtime.h>
#include <cuda_fp16.h>
#include <math.h>
#include <stdint.h>

#define N_NODES 8192
#define F_IN    512
#define F_OUT   64
#define ALPHA   0.2f

#define TJ      64
#define JSPLIT  8
#define JQ      (N_NODES / JSPLIT)   // 1024
#define TILES_B (JQ / TJ)            // 16 tiles per block
#define ROWS_B  64                   // i-rows per block

// SMEM stage layout (bytes)
#define ADJ_STRIDE 272               // 64 ints (256B) + 16B pad (17 chunks)
#define WHB2_OFF   17408             // after 64 adj rows
#define WHB2_STR   272               // 16 chunks of 16B + 16B pad
#define S2T_OFF    26112             // 17408 + 32*272
#define STAGE      26368             // + 256B s2
#define RING       2
#define SMEM_SZ    (STAGE * RING)    // 52736 (x4 blocks = 211KB/SM)

// Scratch (no allocations allowed anywhere)
__device__ float    g_Wh  [N_NODES * F_OUT];
// j-pair-packed fp16 Wh: entry [jp][g2*8+n2] = (Wh[2jp][n2*8+g2], Wh[2jp+1][n2*8+g2])
__device__ __half2  g_WhB2[(N_NODES / 2) * F_OUT];
__device__ float    g_s1  [N_NODES];
__device__ float    g_s2  [N_NODES];
__device__ unsigned g_s2max_bits;    // monotone float key; zero-init = -inf key
__device__ float    g_part [JSPLIT][N_NODES * F_OUT];
__device__ float    g_lpart[JSPLIT][N_NODES];

// ---- helpers ---------------------------------------------------------------
__device__ __forceinline__ uint32_t smem_u32(const void* p) {
    uint32_t r;
    asm("{ .reg .u64 t; cvta.to.shared.u64 t, %1; cvt.u32.u64 %0, t; }"
        : "=r"(r) : "l"(p));
    return r;
}
__device__ __forceinline__ void cp_async16(uint32_t dst, const void* src) {
    asm volatile("cp.async.cg.shared.global [%0], [%1], 16;"
                 :: "r"(dst), "l"(src) : "memory");
}
__device__ __forceinline__ void cp_commit() {
    asm volatile("cp.async.commit_group;" ::: "memory");
}
__device__ __forceinline__ void cp_wait0() {
    asm volatile("cp.async.wait_group 0;" ::: "memory");
}
__device__ __forceinline__ void cp_wait1() {
    asm volatile("cp.async.wait_group 1;" ::: "memory");
}
__device__ __forceinline__ uint32_t to_tf32(float x) {
    uint32_t r;
    asm("cvt.rna.tf32.f32 %0, %1;" : "=r"(r) : "f"(x));
    return r;
}
// pack two f32 into f16x2: lo -> low half, hi -> high half
__device__ __forceinline__ uint32_t f16x2(float lo, float hi) {
    uint32_t r;
    asm("cvt.rn.f16x2.f32 %0, %1, %2;" : "=r"(r) : "f"(hi), "f"(lo));
    return r;
}
// monotone float <-> unsigned key (unsigned order == float order)
__device__ __forceinline__ unsigned f2key(float f) {
    unsigned b = __float_as_uint(f);
    return (b & 0x80000000u) ? ~b : (b | 0x80000000u);
}
__device__ __forceinline__ float key2f(unsigned k) {
    return __uint_as_float((k & 0x80000000u) ? (k ^ 0x80000000u) : ~k);
}
__device__ __forceinline__ void mma_tf32(float* c, uint32_t a0, uint32_t a1,
                                         uint32_t a2, uint32_t a3,
                                         uint32_t b0, uint32_t b1) {
    asm volatile(
        "mma.sync.aligned.m16n8k8.row.col.f32.tf32.tf32.f32 "
        "{%0,%1,%2,%3}, {%4,%5,%6,%7}, {%8,%9}, {%0,%1,%2,%3};"
        : "+f"(c[0]), "+f"(c[1]), "+f"(c[2]), "+f"(c[3])
        : "r"(a0), "r"(a1), "r"(a2), "r"(a3), "r"(b0), "r"(b1));
}
__device__ __forceinline__ void mma_f16(float* c, uint32_t a0, uint32_t a1,
                                        uint32_t a2, uint32_t a3,
                                        uint32_t b0, uint32_t b1) {
    asm volatile(
        "mma.sync.aligned.m16n8k16.row.col.f32.f16.f16.f32 "
        "{%0,%1,%2,%3}, {%4,%5,%6,%7}, {%8,%9}, {%0,%1,%2,%3};"
        : "+f"(c[0]), "+f"(c[1]), "+f"(c[2]), "+f"(c[3])
        : "r"(a0), "r"(a1), "r"(a2), "r"(a3), "r"(b0), "r"(b1));
}

// ---------------------------------------------------------------------------
// Kernel A: Wh = x @ W via tf32 mma.sync. Epilogue also:
//  - packs fp16 g_WhB2 (lane-pair shuffles)
//  - computes s1/s2 rows + global max(s2) (fused former s_kernel)
// ---------------------------------------------------------------------------
#define XS_STR 36
#define WS_STR 72
__global__ __launch_bounds__(256) void wh_kernel(const float* __restrict__ x,
                                                 const float* __restrict__ W,
                                                 const float* __restrict__ A) {
    __shared__ __align__(16) float xs[2][64 * XS_STR];
    __shared__ __align__(16) float ws[2][32 * WS_STR];

    const int tid  = threadIdx.x;
    const int w    = tid >> 5, lane = tid & 31;
    const int wr   = w & 3,    wc   = w >> 2;
    const int g    = lane >> 2, tig = lane & 3;
    const int r0   = blockIdx.x * 64;
    const int r0l  = wr * 16 + g;
    const int r1l  = r0l + 8;

    const uint32_t xs0 = smem_u32(xs);
    const uint32_t ws0 = smem_u32(ws);

    auto prefetch = [&](int s) {
        if (s < 16) {
            int b = s & 1;
            int k0 = s * 32;
            #pragma unroll
            for (int c = tid; c < 512; c += 256) {     // x: 64 rows x 32 k
                int r = c >> 3, q = c & 7;
                cp_async16(xs0 + (b * 64 * XS_STR + r * XS_STR) * 4 + q * 16,
                           x + (size_t)(r0 + r) * F_IN + k0 + q * 4);
            }
            #pragma unroll
            for (int c = tid; c < 512; c += 256) {     // W: 32 k x 64 f
                int r = c >> 4, q = c & 15;
                cp_async16(ws0 + (b * 32 * WS_STR + r * WS_STR) * 4 + q * 16,
                           W + (size_t)(k0 + r) * F_OUT + q * 4);
            }
        }
        cp_commit();
    };

    float acc[4][4] = {};
    prefetch(0);

    for (int s = 0; s < 16; ++s) {
        prefetch(s + 1);
        cp_wait1();
        __syncthreads();

        const float* xp = &xs[s & 1][0];
        const float* wp = &ws[s & 1][0];

        #pragma unroll
        for (int kc = 0; kc < 4; ++kc) {
            uint32_t a0 = to_tf32(xp[r0l * XS_STR + kc * 8 + tig]);
            uint32_t a1 = to_tf32(xp[r1l * XS_STR + kc * 8 + tig]);
            uint32_t a2 = to_tf32(xp[r0l * XS_STR + kc * 8 + tig + 4]);
            uint32_t a3 = to_tf32(xp[r1l * XS_STR + kc * 8 + tig + 4]);
            #pragma unroll
            for (int n = 0; n < 4; ++n) {
                int f = wc * 32 + n * 8 + g;
                uint32_t b0 = to_tf32(wp[(kc * 8 + tig)     * WS_STR + f]);
                uint32_t b1 = to_tf32(wp[(kc * 8 + tig + 4) * WS_STR + f]);
                mma_tf32(acc[n], a0, a1, a2, a3, b0, b1);
            }
        }
        __syncthreads();
    }

    // fp32 Wh stores
    #pragma unroll
    for (int n = 0; n < 4; ++n) {
        int f = wc * 32 + n * 8 + tig * 2;
        *(float2*)&g_Wh[(size_t)(r0 + r0l) * F_OUT + f] = make_float2(acc[n][0], acc[n][1]);
        *(float2*)&g_Wh[(size_t)(r0 + r1l) * F_OUT + f] = make_float2(acc[n][2], acc[n][3]);
    }

    // fused fp16 pack: even-g lanes pair with lane+4 (row r0l+1 / r1l+1)
    {
        float pacc[4][4];
        #pragma unroll
        for (int n = 0; n < 4; ++n)
            #pragma unroll
            for (int q = 0; q < 4; ++q)
                pacc[n][q] = __shfl_down_sync(0xFFFFFFFFu, acc[n][q], 4);

        if ((g & 1) == 0) {
            int jp0 = (r0 + r0l) >> 1;
            int jp1 = jp0 + 4;
            uint32_t pk[4][4];
            #pragma unroll
            for (int n = 0; n < 4; ++n) {
                pk[0][n] = f16x2(acc[n][0], pacc[n][0]);
                pk[1][n] = f16x2(acc[n][1], pacc[n][1]);
                pk[2][n] = f16x2(acc[n][2], pacc[n][2]);
                pk[3][n] = f16x2(acc[n][3], pacc[n][3]);
            }
            int c0 = tig * 16 + wc * 4;
            *(uint4*)&g_WhB2[(size_t)jp0 * F_OUT + c0]     = *(uint4*)pk[0];
            *(uint4*)&g_WhB2[(size_t)jp0 * F_OUT + c0 + 8] = *(uint4*)pk[1];
            *(uint4*)&g_WhB2[(size_t)jp1 * F_OUT + c0]     = *(uint4*)pk[2];
            *(uint4*)&g_WhB2[(size_t)jp1 * F_OUT + c0 + 8] = *(uint4*)pk[3];
        }
    }

    // fused s1/s2/s2max (former s_kernel; same fp32 values as g_Wh)
    {
        float* red = (float*)xs;               // [0..511] s1, [512..1023] s2
        float p10 = 0.f, p20 = 0.f, p11 = 0.f, p21 = 0.f;
        #pragma unroll
        for (int n = 0; n < 4; ++n) {
            int f = wc * 32 + n * 8 + tig * 2;
            float a1f = A[f],          a1g = A[f + 1];
            float a2f = A[F_OUT + f],  a2g = A[F_OUT + f + 1];
            p10 += acc[n][0] * a1f + acc[n][1] * a1g;
            p20 += acc[n][0] * a2f + acc[n][1] * a2g;
            p11 += acc[n][2] * a1f + acc[n][3] * a1g;
            p21 += acc[n][2] * a2f + acc[n][3] * a2g;
        }
        int idx = wc * 4 + tig;
        red[r0l * 8 + idx]       = p10;
        red[512 + r0l * 8 + idx] = p20;
        red[r1l * 8 + idx]       = p11;
        red[512 + r1l * 8 + idx] = p21;
        __syncthreads();

        if (tid < 64) {
            float s1v = 0.f, s2v = 0.f;
            #pragma unroll
            for (int k = 0; k < 8; ++k) {
                s1v += red[tid * 8 + k];
                s2v += red[512 + tid * 8 + k];
            }
            g_s1[r0 + tid] = s1v;
            g_s2[r0 + tid] = s2v;
            float m = s2v;
            #pragma unroll
            for (int off = 16; off; off >>= 1)
                m = fmaxf(m, __shfl_xor_sync(0xFFFFFFFFu, m, off));
            if ((tid & 31) == 0) red[1024 + (tid >> 5)] = m;
        }
        __syncthreads();
        if (tid == 0)
            atomicMax(&g_s2max_bits, f2key(fmaxf(red[1024], red[1025])));
    }
}

// ---------------------------------------------------------------------------
// Kernel C: fused attention via mma.sync fp16 (m16n8k16).
// grid = 128 i-blocks x 8 j-slices = 1024 blocks, 4 blocks/SM.
// TJ=64, RING=2: one barrier per 64-j tile.
// Pipeline: cp_wait0 (own group t drained) -> bar (publish t; all warps past
// compute(t-1)) -> prefetch(t+1) (slot t-1, safe) -> compute(t) overlapped.
// ---------------------------------------------------------------------------
__global__ __launch_bounds__(256, 4) void attn_kernel(const int* __restrict__ adj) {
    extern __shared__ __align__(1024) char smem[];
    const int tid  = threadIdx.x;
    const int w    = tid >> 5, lane = tid & 31;
    const int wr   = w & 3,    jh   = w >> 2;
    const int g    = lane >> 2, tig = lane & 3;
    const int i0   = (blockIdx.x >> 3) * ROWS_B;
    const int qh   = blockIdx.x & 7;
    const int j0b  = qh * JQ;
    const int r0l  = wr * 16 + g;
    const int r1l  = r0l + 8;

    const uint32_t sb = smem_u32(smem);

    // prefetch-thread invariants
    const int pr  = tid >> 2, pc  = tid & 3;      // adj: row, chunk base
    const int wrw = tid >> 3, wc8 = tid & 7;      // WhB2: jp row, src chunk base
    const uint32_t adj_dst = sb + pr * ADJ_STRIDE + pc * 16;
    const uint32_t whrow   = sb + WHB2_OFF + wrw * WHB2_STR;
    const uint32_t wh_dst0 = whrow + (((wc8     + (wrw & 2)) & 15) * 16);
    const uint32_t wh_dst1 = whrow + (((wc8 + 8 + (wrw & 2)) & 15) * 16);
    const int      a_row0  = r0l * ADJ_STRIDE;
    const int      a_row1  = r1l * ADJ_STRIDE;

    const int* adj_src   = adj + (size_t)(i0 + pr) * N_NODES + j0b + pc * 4;
    const char* wh_src0  = (const char*)g_WhB2 + ((size_t)(j0b >> 1) + wrw) * 256 + wc8 * 16;
    const float* s2_src  = g_s2 + j0b + (tid & 15) * 4;

    auto prefetch = [&](int t) {
        if (t < TILES_B) {
            uint32_t base = (uint32_t)((t & 1) * STAGE);
            int jo = t * TJ;                       // int offset into slice
            #pragma unroll
            for (int q = 0; q < 4; ++q)            // adj: 4 chunks/thread
                cp_async16(adj_dst + base + q * 64, adj_src + jo + q * 16);
            const char* wsrc = wh_src0 + (size_t)t * 8192;
            cp_async16(wh_dst0 + base, wsrc);
            cp_async16(wh_dst1 + base, wsrc + 128);
            if (tid < 16)
                cp_async16(sb + S2T_OFF + base + tid * 16, s2_src + jo);
        }
        cp_commit();
    };

    const float s1_0 = g_s1[i0 + r0l];
    const float s1_1 = g_s1[i0 + r1l];
    const float s2m  = key2f(g_s2max_bits);
    const float m0 = fmaxf(s1_0 + s2m, ALPHA * (s1_0 + s2m));
    const float m1 = fmaxf(s1_1 + s2m, ALPHA * (s1_1 + s2m));

    float acc[8][4] = {};
    float sum0 = 0.f, sum1 = 0.f;

    prefetch(0);

    const int d = tig & 2;
    const uint32_t pLo = (uint32_t)(((2 * g + d) & 15) * 16);
    const uint32_t pHi = (uint32_t)(((2 * g + 1 + d) & 15) * 16);

    for (int t = 0; t < TILES_B; ++t) {
        cp_wait0();
        __syncthreads();
        prefetch(t + 1);

        const char*  base = smem + (t & 1) * STAGE;
        const float* s2p  = (const float*)(base + S2T_OFF);

        #pragma unroll
        for (int kc = 0; kc < 2; ++kc) {
            const int jo = jh * 32 + kc * 16;
            const int jA = jo + 2 * tig;
            const int jB = jA + 8;

            float2 s2a = *(const float2*)(s2p + jA);
            float2 s2b = *(const float2*)(s2p + jB);
            int2 A0a = *(const int2*)(base + a_row0 + jA * 4);
            int2 A0b = *(const int2*)(base + a_row0 + jB * 4);
            int2 A1a = *(const int2*)(base + a_row1 + jA * 4);
            int2 A1b = *(const int2*)(base + a_row1 + jB * 4);

            float t00 = s1_0 + s2a.x, t01 = s1_0 + s2a.y;
            float t02 = s1_0 + s2b.x, t03 = s1_0 + s2b.y;
            float t10 = s1_1 + s2a.x, t11 = s1_1 + s2a.y;
            float t12 = s1_1 + s2b.x, t13 = s1_1 + s2b.y;
            float w00 = (A0a.x > 0) ? __expf(fmaxf(t00, ALPHA * t00) - m0) : 0.f;
            float w01 = (A0a.y > 0) ? __expf(fmaxf(t01, ALPHA * t01) - m0) : 0.f;
            float w02 = (A0b.x > 0) ? __expf(fmaxf(t02, ALPHA * t02) - m0) : 0.f;
            float w03 = (A0b.y > 0) ? __expf(fmaxf(t03, ALPHA * t03) - m0) : 0.f;
            float w10 = (A1a.x > 0) ? __expf(fmaxf(t10, ALPHA * t10) - m1) : 0.f;
            float w11 = (A1a.y > 0) ? __expf(fmaxf(t11, ALPHA * t11) - m1) : 0.f;
            float w12 = (A1b.x > 0) ? __expf(fmaxf(t12, ALPHA * t12) - m1) : 0.f;
            float w13 = (A1b.y > 0) ? __expf(fmaxf(t13, ALPHA * t13) - m1) : 0.f;
            sum0 += (w00 + w01) + (w02 + w03);
            sum1 += (w10 + w11) + (w12 + w13);
            uint32_t a0 = f16x2(w00, w01);
            uint32_t a1 = f16x2(w10, w11);
            uint32_t a2 = f16x2(w02, w03);
            uint32_t a3 = f16x2(w12, w13);

            const int jp0 = jh * 16 + kc * 8 + tig;
            const uint32_t bOff0 = (uint32_t)(WHB2_OFF + jp0 * WHB2_STR);
            const uint32_t bOff1 = bOff0 + 4 * WHB2_STR;
            uint4 bl0 = *(const uint4*)(base + bOff0 + pLo);
            uint4 bh0 = *(const uint4*)(base + bOff0 + pHi);
            uint4 bl1 = *(const uint4*)(base + bOff1 + pLo);
            uint4 bh1 = *(const uint4*)(base + bOff1 + pHi);

            mma_f16(acc[0], a0, a1, a2, a3, bl0.x, bl1.x);
            mma_f16(acc[1], a0, a1, a2, a3, bl0.y, bl1.y);
            mma_f16(acc[2], a0, a1, a2, a3, bl0.z, bl1.z);
            mma_f16(acc[3], a0, a1, a2, a3, bl0.w, bl1.w);
            mma_f16(acc[4], a0, a1, a2, a3, bh0.x, bh1.x);
            mma_f16(acc[5], a0, a1, a2, a3, bh0.y, bh1.y);
            mma_f16(acc[6], a0, a1, a2, a3, bh0.z, bh1.z);
            mma_f16(acc[7], a0, a1, a2, a3, bh0.w, bh1.w);
        }
    }

    // ---- epilogue: merge the two j-half partials -------------------------
    __syncthreads();                       // all tiles done; stage smem free
    float* eS    = (float*)smem;           // 64 x 66 floats (16.9 KB)
    float* lsumS = (float*)(smem + 64 * 66 * 4);  // 2 x 64 floats

    sum0 += __shfl_xor_sync(0xFFFFFFFFu, sum0, 1);
    sum0 += __shfl_xor_sync(0xFFFFFFFFu, sum0, 2);
    sum1 += __shfl_xor_sync(0xFFFFFFFFu, sum1, 1);
    sum1 += __shfl_xor_sync(0xFFFFFFFFu, sum1, 2);
    if (tig == 0) {
        lsumS[jh * 64 + r0l] = sum0;
        lsumS[jh * 64 + r1l] = sum1;
    }

    if (jh == 0) {
        #pragma unroll
        for (int n = 0; n < 8; ++n) {
            *(float2*)&eS[r0l * 66 + n * 8 + tig * 2] = make_float2(acc[n][0], acc[n][1]);
            *(float2*)&eS[r1l * 66 + n * 8 + tig * 2] = make_float2(acc[n][2], acc[n][3]);
        }
    }
    __syncthreads();
    if (jh == 1) {
        #pragma unroll
        for (int n = 0; n < 8; ++n) {
            int f = n * 8 + tig * 2;
            float2 p0 = *(const float2*)&eS[r0l * 66 + f];
            float2 p1 = *(const float2*)&eS[r1l * 66 + f];
            *(float2*)&g_part[qh][(size_t)(i0 + r0l) * F_OUT + f] =
                make_float2(acc[n][0] + p0.x, acc[n][1] + p0.y);
            *(float2*)&g_part[qh][(size_t)(i0 + r1l) * F_OUT + f] =
                make_float2(acc[n][2] + p1.x, acc[n][3] + p1.y);
        }
        if (tig == 0) {
            g_lpart[qh][i0 + r0l] = lsumS[r0l] + lsumS[64 + r0l];
            g_lpart[qh][i0 + r1l] = lsumS[r1l] + lsumS[64 + r1l];
        }
    }
}

// ---------------------------------------------------------------------------
// Kernel D: out = (sum_q part_q) / (sum_q l_q) + bias
// ---------------------------------------------------------------------------
__global__ __launch_bounds__(256) void combine_kernel(const float* __restrict__ bias,
                                                      float* __restrict__ out) {
    int idx = blockIdx.x * 256 + threadIdx.x;    // 8192*16 float4 slots
    int i  = idx >> 4;
    int fq = idx & 15;
    size_t off = (size_t)i * F_OUT + fq * 4;

    float4 p = *(const float4*)&g_part[0][off];
    float  l = g_lpart[0][i];
    #pragma unroll
    for (int q = 1; q < JSPLIT; ++q) {
        float4 pq = *(const float4*)&g_part[q][off];
        p.x += pq.x; p.y += pq.y; p.z += pq.z; p.w += pq.w;
        l += g_lpart[q][i];
    }
    float inv = 1.0f / l;
    float4 bz = *(const float4*)&bias[fq * 4];
    float4 r;
    r.x = p.x * inv + bz.x;
    r.y = p.y * inv + bz.y;
    r.z = p.z * inv + bz.z;
    r.w = p.w * inv + bz.w;
    *(float4*)&out[off] = r;
}

// ---------------------------------------------------------------------------
extern "C" void kernel_launch(void* const* d_in, const int* in_sizes, int n_in,
                              void* d_out, int out_size) {
    const float* x    = (const float*)d_in[0];
    const int*   adj  = (const int*)  d_in[1];
    const float* W    = (const float*)d_in[2];
    const float* bias = (const float*)d_in[3];
    const float* A    = (const float*)d_in[4];
    float*       out  = (float*)d_out;

    cudaFuncSetAttribute(attn_kernel,
                         cudaFuncAttributeMaxDynamicSharedMemorySize, SMEM_SZ);

    wh_kernel     <<<N_NODES / 64, 256>>>(x, W, A);
    attn_kernel   <<<(N_NODES / ROWS_B) * JSPLIT, 256, SMEM_SZ>>>(adj);
    combine_kernel<<<N_NODES * 16 / 256, 256>>>(bias, out);
}